// round 5
// baseline (speedup 1.0000x reference)
#include <cuda_runtime.h>
#include <math.h>

// ---------------------------------------------------------------------------
// ReservoirBlock: B=8, T=2048, D=768, R=3072, HR=768, HF=3072.  All fp32.
// ---------------------------------------------------------------------------

#define NTOK 16384          // B*T
#define DIM  768
#define RDIM 3072
#define TLEN 2048
#define NB   8

#define RBLK 144            // persistent blocks for recurrence
#define SKC  12             // k-chunks
#define KCW  256            // k per chunk

typedef unsigned long long ull;

// ------------------------------ scratch ------------------------------------
__device__ __align__(16) float g_buf1[(size_t)NTOK * RDIM];   // xu -> r_raw (in place)
__device__ __align__(16) float g_buf2[(size_t)NTOK * RDIM];   // rln ; later ffn hidden
__device__ __align__(16) float g_ln  [(size_t)NTOK * DIM];    // LN(x) ; later LN(m)
__device__ __align__(16) float g_t1  [(size_t)NTOK * DIM];    // res-mlp mid ; later f
__device__ __align__(16) float g_r   [(size_t)NTOK * DIM];
__device__ __align__(16) float g_gz  [(size_t)NTOK * 2 * DIM];
__device__ __align__(16) float g_g1  [(size_t)NTOK * DIM];
__device__ __align__(16) float g_g   [(size_t)NTOK * DIM];
__device__ __align__(16) float g_m   [(size_t)NTOK * DIM];
__device__ __align__(16) float g_hbuf[2][RDIM * NB];          // ping-pong state [k][b]
__device__ __align__(16) float2 g_part[SKC * RDIM * 4];       // k-chunk partials
__device__ unsigned g_bar_count;                              // stays 0 between runs
__device__ unsigned g_bar_sense;                              // monotonic

// --------------------------- f32x2 helpers ---------------------------------
__device__ __forceinline__ ull pk2(float x, float y) {
    ull r; asm("mov.b64 %0, {%1, %2};" : "=l"(r) : "f"(x), "f"(y)); return r;
}
__device__ __forceinline__ void fma2(ull &d, ull a, ull b) {
    asm("fma.rn.f32x2 %0, %1, %2, %0;" : "+l"(d) : "l"(a), "l"(b));
}
__device__ __forceinline__ ull add2(ull a, ull b) {
    ull d; asm("add.rn.f32x2 %0, %1, %2;" : "=l"(d) : "l"(a), "l"(b)); return d;
}
__device__ __forceinline__ float2 up2(ull v) {
    float2 f; asm("mov.b64 {%0, %1}, %2;" : "=f"(f.x), "=f"(f.y) : "l"(v)); return f;
}

// --------------------------- grid barrier ----------------------------------
__device__ __forceinline__ void grid_bar(unsigned &sense) {
    sense += 1;
    __threadfence();
    __syncthreads();
    if (threadIdx.x == 0) {
        if (atomicAdd(&g_bar_count, 1u) == RBLK - 1u) {
            g_bar_count = 0u;
            __threadfence();
            *(volatile unsigned *)&g_bar_sense = sense;
        } else {
            while (*(volatile unsigned *)&g_bar_sense != sense) { }
        }
    }
    __syncthreads();
}

// --------------------------- init h ----------------------------------------
__global__ void zero_h_kernel() {
    int i = blockIdx.x * blockDim.x + threadIdx.x;
    if (i < RDIM * NB) g_hbuf[0][i] = 0.0f;
}

// --------------------------- recurrence ------------------------------------
// Persistent: 144 blocks = 12 j-tiles (256 cols) x 12 k-chunks (256 k).
// Thread: 4 consecutive cols, 8 batches packed as 4 f32x2 accumulators.
__global__ void __launch_bounds__(256)
reservoir_kernel(const float* __restrict__ W, float* __restrict__ xu)
{
    __shared__ float h_s[KCW * NB];     // 8 KB: h slice, layout [k][b]
    __shared__ ull   red[256 * 17];     // 34 KB: cross-kgroup reduction

    const int tid = threadIdx.x;
    const int bid = blockIdx.x;
    const int jt  = bid / SKC;
    const int kc  = bid % SKC;
    const int l64 = tid & 63;
    const int kg  = tid >> 6;
    const int col = jt * 256 + l64 * 4;

    unsigned sense = *(volatile unsigned *)&g_bar_sense;   // base (stable pre-barrier)

    #pragma unroll 1
    for (int t = 0; t < TLEN; ++t) {
        const int cur = t & 1;
        const int nxt = cur ^ 1;

        // stage h slice (cross-block data -> .cg to bypass stale L1)
        {
            const float4* src = (const float4*)(g_hbuf[cur] + kc * KCW * NB);
            float4* dst = (float4*)h_s;
            dst[tid]       = __ldcg(src + tid);
            dst[tid + 256] = __ldcg(src + tid + 256);
        }
        __syncthreads();

        ull acc[16];
        #pragma unroll
        for (int q = 0; q < 16; ++q) acc[q] = 0ull;

        const float* wp = W + (size_t)(kc * KCW + kg * 64) * RDIM + col;
        const float* hp = h_s + (kg * 64) * NB;
        #pragma unroll 4
        for (int i = 0; i < 64; ++i) {
            const float4 w4 = *(const float4*)(wp + (size_t)i * RDIM);
            const ulonglong2 hA = *(const ulonglong2*)(hp + i * NB);
            const ulonglong2 hB = *(const ulonglong2*)(hp + i * NB + 4);
            ull s;
            s = pk2(w4.x, w4.x);
            fma2(acc[0],  s, hA.x); fma2(acc[1],  s, hA.y); fma2(acc[2],  s, hB.x); fma2(acc[3],  s, hB.y);
            s = pk2(w4.y, w4.y);
            fma2(acc[4],  s, hA.x); fma2(acc[5],  s, hA.y); fma2(acc[6],  s, hB.x); fma2(acc[7],  s, hB.y);
            s = pk2(w4.z, w4.z);
            fma2(acc[8],  s, hA.x); fma2(acc[9],  s, hA.y); fma2(acc[10], s, hB.x); fma2(acc[11], s, hB.y);
            s = pk2(w4.w, w4.w);
            fma2(acc[12], s, hA.x); fma2(acc[13], s, hA.y); fma2(acc[14], s, hB.x); fma2(acc[15], s, hB.y);
        }

        #pragma unroll
        for (int q = 0; q < 16; ++q) red[tid * 17 + q] = acc[q];
        __syncthreads();

        if (kg == 0) {  // reduce the 4 k-groups, write chunk partials
            #pragma unroll
            for (int q = 0; q < 16; ++q) {
                ull v = red[l64 * 17 + q];
                v = add2(v, red[(l64 + 64)  * 17 + q]);
                v = add2(v, red[(l64 + 128) * 17 + q]);
                v = add2(v, red[(l64 + 192) * 17 + q]);
                const int c = q >> 2, p = q & 3;
                __stcg(&g_part[(kc * RDIM + col + c) * 4 + p], up2(v));
            }
        }
        grid_bar(sense);

        // finalize: sum 12 chunk partials, add xu, tanh, write r + next h
        {
            const int g = bid * 256 + tid;
            if (g < RDIM * 4) {
                const int j = g >> 2, bp = g & 3;
                float sx = 0.0f, sy = 0.0f;
                #pragma unroll
                for (int k2 = 0; k2 < SKC; ++k2) {
                    const float2 p = __ldcg(&g_part[(k2 * RDIM + j) * 4 + bp]);
                    sx += p.x; sy += p.y;
                }
                const size_t i0 = ((size_t)(2 * bp) * TLEN + t) * RDIM + j;
                const size_t i1 = i0 + (size_t)TLEN * RDIM;
                const float v0 = tanhf(sx + xu[i0]);
                const float v1 = tanhf(sy + xu[i1]);
                xu[i0] = v0;   // r stored in place of xu
                xu[i1] = v1;
                __stcg((float2*)(g_hbuf[nxt] + j * NB + 2 * bp), make_float2(v0, v1));
            }
        }
        grid_bar(sense);
    }
}

// --------------------------- activations -----------------------------------
template<int ACT>
__device__ __forceinline__ float act_apply(float v) {
    if (ACT == 1) return 0.5f * v * (1.0f + erff(v * 0.70710678118654752440f)); // exact gelu
    if (ACT == 2) return 1.0f / (1.0f + expf(-v));                              // sigmoid
    return v;
}

// --------------------------- SGEMM 128x128x16 ------------------------------
// C = act(A @ Bw + bias) * exp(*scale_log). A:MxK, Bw:KxN row-major.
// All M,N multiples of 128, K multiples of 16 (no bounds checks).
template<int ACT>
__global__ void __launch_bounds__(256)
sgemm_kernel(const float* __restrict__ A, const float* __restrict__ Bw,
             const float* __restrict__ bias, float* __restrict__ C,
             int M, int N, int K,
             const float* __restrict__ scale_log,
             const float* __restrict__ guard)
{
    if (guard && guard[0] == 0.0f) return;
    __shared__ float As[16 * 132];   // padded: A^T tile
    __shared__ float Bs[16 * 128];

    const int tid = threadIdx.x;
    const int bx = blockIdx.x, by = blockIdx.y;
    const int tx = tid & 15, ty = tid >> 4;
    const int arow = tid >> 2, acol = (tid & 3) << 2;
    const int brow = tid >> 4, bcol = (tid & 15) << 2;
    const size_t abase = (size_t)(by * 128) * K;
    const int cbase = bx * 128;

    ull acc[8][4];
    #pragma unroll
    for (int i = 0; i < 8; ++i)
        #pragma unroll
        for (int j = 0; j < 4; ++j) acc[i][j] = 0ull;

    for (int ko = 0; ko < K; ko += 16) {
        const float4 av0 = *(const float4*)(A + abase + (size_t)arow * K + ko + acol);
        const float4 av1 = *(const float4*)(A + abase + (size_t)(arow + 64) * K + ko + acol);
        const float4 bv0 = *(const float4*)(Bw + (size_t)(ko + brow) * N + cbase + bcol);
        const float4 bv1 = *(const float4*)(Bw + (size_t)(ko + brow) * N + cbase + bcol + 64);
        __syncthreads();
        As[(acol + 0) * 132 + arow] = av0.x;
        As[(acol + 1) * 132 + arow] = av0.y;
        As[(acol + 2) * 132 + arow] = av0.z;
        As[(acol + 3) * 132 + arow] = av0.w;
        As[(acol + 0) * 132 + arow + 64] = av1.x;
        As[(acol + 1) * 132 + arow + 64] = av1.y;
        As[(acol + 2) * 132 + arow + 64] = av1.z;
        As[(acol + 3) * 132 + arow + 64] = av1.w;
        *(float4*)&Bs[brow * 128 + bcol]      = bv0;
        *(float4*)&Bs[brow * 128 + bcol + 64] = bv1;
        __syncthreads();

        #pragma unroll
        for (int kk = 0; kk < 16; ++kk) {
            const float4 a0 = *(const float4*)&As[kk * 132 + ty * 4];
            const float4 a1 = *(const float4*)&As[kk * 132 + 64 + ty * 4];
            const ulonglong2 b01 = *(const ulonglong2*)&Bs[kk * 128 + tx * 4];
            const ulonglong2 b23 = *(const ulonglong2*)&Bs[kk * 128 + tx * 4 + 64];
            ull s;
            s = pk2(a0.x, a0.x); fma2(acc[0][0], s, b01.x); fma2(acc[0][1], s, b01.y); fma2(acc[0][2], s, b23.x); fma2(acc[0][3], s, b23.y);
            s = pk2(a0.y, a0.y); fma2(acc[1][0], s, b01.x); fma2(acc[1][1], s, b01.y); fma2(acc[1][2], s, b23.x); fma2(acc[1][3], s, b23.y);
            s = pk2(a0.z, a0.z); fma2(acc[2][0], s, b01.x); fma2(acc[2][1], s, b01.y); fma2(acc[2][2], s, b23.x); fma2(acc[2][3], s, b23.y);
            s = pk2(a0.w, a0.w); fma2(acc[3][0], s, b01.x); fma2(acc[3][1], s, b01.y); fma2(acc[3][2], s, b23.x); fma2(acc[3][3], s, b23.y);
            s = pk2(a1.x, a1.x); fma2(acc[4][0], s, b01.x); fma2(acc[4][1], s, b01.y); fma2(acc[4][2], s, b23.x); fma2(acc[4][3], s, b23.y);
            s = pk2(a1.y, a1.y); fma2(acc[5][0], s, b01.x); fma2(acc[5][1], s, b01.y); fma2(acc[5][2], s, b23.x); fma2(acc[5][3], s, b23.y);
            s = pk2(a1.z, a1.z); fma2(acc[6][0], s, b01.x); fma2(acc[6][1], s, b01.y); fma2(acc[6][2], s, b23.x); fma2(acc[6][3], s, b23.y);
            s = pk2(a1.w, a1.w); fma2(acc[7][0], s, b01.x); fma2(acc[7][1], s, b01.y); fma2(acc[7][2], s, b23.x); fma2(acc[7][3], s, b23.y);
        }
    }

    float sc = 1.0f;
    if (scale_log) sc = expf(scale_log[0]);
    float4 bb0 = make_float4(0.f, 0.f, 0.f, 0.f), bb1 = bb0;
    if (bias) {
        bb0 = *(const float4*)(bias + cbase + tx * 4);
        bb1 = *(const float4*)(bias + cbase + tx * 4 + 64);
    }
    #pragma unroll
    for (int i = 0; i < 8; ++i) {
        const int r = by * 128 + ((i < 4) ? (ty * 4 + i) : (64 + ty * 4 + i - 4));
        const float2 p0 = up2(acc[i][0]), p1 = up2(acc[i][1]);
        const float2 p2 = up2(acc[i][2]), p3 = up2(acc[i][3]);
        float4 o0, o1;
        o0.x = act_apply<ACT>(p0.x + bb0.x) * sc;
        o0.y = act_apply<ACT>(p0.y + bb0.y) * sc;
        o0.z = act_apply<ACT>(p1.x + bb0.z) * sc;
        o0.w = act_apply<ACT>(p1.y + bb0.w) * sc;
        o1.x = act_apply<ACT>(p2.x + bb1.x) * sc;
        o1.y = act_apply<ACT>(p2.y + bb1.y) * sc;
        o1.z = act_apply<ACT>(p3.x + bb1.z) * sc;
        o1.w = act_apply<ACT>(p3.y + bb1.w) * sc;
        *(float4*)(C + (size_t)r * N + cbase + tx * 4)      = o0;
        *(float4*)(C + (size_t)r * N + cbase + tx * 4 + 64) = o1;
    }
}

// --------------------------- LayerNorm -------------------------------------
__device__ __forceinline__ void blk_reduce2(float &s, float &s2) {
    const unsigned m = 0xffffffffu;
    #pragma unroll
    for (int o = 16; o; o >>= 1) { s += __shfl_xor_sync(m, s, o); s2 += __shfl_xor_sync(m, s2, o); }
    __shared__ float sh[16];
    const int w = threadIdx.x >> 5, l = threadIdx.x & 31;
    if (l == 0) { sh[w] = s; sh[8 + w] = s2; }
    __syncthreads();
    if (threadIdx.x < 32) {
        s  = (l < 8) ? sh[l]     : 0.0f;
        s2 = (l < 8) ? sh[8 + l] : 0.0f;
        #pragma unroll
        for (int o = 4; o; o >>= 1) { s += __shfl_xor_sync(m, s, o); s2 += __shfl_xor_sync(m, s2, o); }
        if (l == 0) { sh[0] = s; sh[8] = s2; }
    }
    __syncthreads();
    s = sh[0]; s2 = sh[8];
}

template<int COLS>
__global__ void __launch_bounds__(256)
ln_kernel(const float* __restrict__ in, const float* __restrict__ w,
          const float* __restrict__ bb, float* __restrict__ out,
          const float* __restrict__ guard)
{
    if (guard && guard[0] == 0.0f) return;
    constexpr int E = COLS / 256;
    const size_t base = (size_t)blockIdx.x * COLS;
    const int tid = threadIdx.x;
    float v[E];
    float s = 0.0f, s2 = 0.0f;
    #pragma unroll
    for (int e = 0; e < E; ++e) {
        const float x = in[base + e * 256 + tid];
        v[e] = x; s += x; s2 += x * x;
    }
    blk_reduce2(s, s2);
    const float mu = s * (1.0f / COLS);
    const float var = s2 * (1.0f / COLS) - mu * mu;
    const float rs = rsqrtf(var + 1e-5f);
    #pragma unroll
    for (int e = 0; e < E; ++e) {
        const int i = e * 256 + tid;
        out[base + i] = (v[e] - mu) * rs * w[i] + bb[i];
    }
}

// LN over concat([x, r]) without materializing the concat
__global__ void __launch_bounds__(256)
ln_concat_kernel(const float* __restrict__ x, const float* __restrict__ r,
                 const float* __restrict__ w, const float* __restrict__ bb,
                 float* __restrict__ out)
{
    constexpr int COLS = 2 * DIM;
    constexpr int E = COLS / 256;
    const int row = blockIdx.x;
    const int tid = threadIdx.x;
    const size_t bx = (size_t)row * DIM;
    const size_t bo = (size_t)row * COLS;
    float v[E];
    float s = 0.0f, s2 = 0.0f;
    #pragma unroll
    for (int e = 0; e < E; ++e) {
        const int i = e * 256 + tid;
        const float val = (i < DIM) ? x[bx + i] : r[bx + i - DIM];
        v[e] = val; s += val; s2 += val * val;
    }
    blk_reduce2(s, s2);
    const float mu = s * (1.0f / COLS);
    const float var = s2 * (1.0f / COLS) - mu * mu;
    const float rs = rsqrtf(var + 1e-5f);
    #pragma unroll
    for (int e = 0; e < E; ++e) {
        const int i = e * 256 + tid;
        out[bo + i] = (v[e] - mu) * rs * w[i] + bb[i];
    }
}

// --------------------------- elementwise -----------------------------------
__global__ void combine_kernel(const float* __restrict__ g, const float* __restrict__ r,
                               const float* __restrict__ x, float* __restrict__ m)
{
    const size_t i = (size_t)blockIdx.x * blockDim.x + threadIdx.x;
    const float gv = g[i];
    m[i] = gv * r[i] + (1.0f - gv) * x[i];
}

__global__ void final_kernel(const float* __restrict__ m, const float* __restrict__ f,
                             const float* __restrict__ alpha, float* __restrict__ out)
{
    const size_t i = (size_t)blockIdx.x * blockDim.x + threadIdx.x;
    const float a = alpha[0];
    float v = m[i];
    if (a != 0.0f) v += a * f[i];
    out[i] = v;
}

// --------------------------- launch ----------------------------------------
extern "C" void kernel_launch(void* const* d_in, const int* in_sizes, int n_in,
                              void* d_out, int out_size)
{
    (void)in_sizes; (void)n_in; (void)out_size;
    const float* x         = (const float*)d_in[0];
    const float* ln_in_w   = (const float*)d_in[1];
    const float* ln_in_b   = (const float*)d_in[2];
    const float* U         = (const float*)d_in[3];
    const float* W         = (const float*)d_in[4];
    const float* res_ln_w  = (const float*)d_in[5];
    const float* res_ln_b  = (const float*)d_in[6];
    const float* res_w1    = (const float*)d_in[7];
    const float* res_b1    = (const float*)d_in[8];
    const float* res_w2    = (const float*)d_in[9];
    const float* res_b2    = (const float*)d_in[10];
    const float* res_logsc = (const float*)d_in[11];
    const float* mix_ln_w  = (const float*)d_in[12];
    const float* mix_ln_b  = (const float*)d_in[13];
    const float* gate_w1   = (const float*)d_in[14];
    const float* gate_b1   = (const float*)d_in[15];
    const float* gate_w2   = (const float*)d_in[16];
    const float* gate_b2   = (const float*)d_in[17];
    const float* ffn_ln_w  = (const float*)d_in[18];
    const float* ffn_ln_b  = (const float*)d_in[19];
    const float* ffn_w1    = (const float*)d_in[20];
    const float* ffn_b1    = (const float*)d_in[21];
    const float* ffn_w2    = (const float*)d_in[22];
    const float* ffn_b2    = (const float*)d_in[23];
    const float* ffn_alpha = (const float*)d_in[24];
    float* out = (float*)d_out;

    float *buf1, *buf2, *lnb, *t1b, *rb, *gzb, *g1b, *gb, *mb;
    cudaGetSymbolAddress((void**)&buf1, g_buf1);
    cudaGetSymbolAddress((void**)&buf2, g_buf2);
    cudaGetSymbolAddress((void**)&lnb,  g_ln);
    cudaGetSymbolAddress((void**)&t1b,  g_t1);
    cudaGetSymbolAddress((void**)&rb,   g_r);
    cudaGetSymbolAddress((void**)&gzb,  g_gz);
    cudaGetSymbolAddress((void**)&g1b,  g_g1);
    cudaGetSymbolAddress((void**)&gb,   g_g);
    cudaGetSymbolAddress((void**)&mb,   g_m);

    const int nelem = NTOK * DIM;

    // 0. reset recurrent state
    zero_h_kernel<<<96, 256>>>();
    // 1. h = LN(x)
    ln_kernel<DIM><<<NTOK, 256>>>(x, ln_in_w, ln_in_b, lnb, nullptr);
    // 2. xu = h @ U   (no bias)
    sgemm_kernel<0><<<dim3(RDIM / 128, NTOK / 128), 256>>>(
        lnb, U, nullptr, buf1, NTOK, RDIM, DIM, nullptr, nullptr);
    // 3. recurrence (writes r over xu in place)
    reservoir_kernel<<<RBLK, 256>>>(W, buf1);
    // 4. rln = LN(r)
    ln_kernel<RDIM><<<NTOK, 256>>>(buf1, res_ln_w, res_ln_b, buf2, nullptr);
    // 5. t1 = gelu(rln @ res_w1 + b1)
    sgemm_kernel<1><<<dim3(DIM / 128, NTOK / 128), 256>>>(
        buf2, res_w1, res_b1, t1b, NTOK, DIM, RDIM, nullptr, nullptr);
    // 6. r = exp(log_scale) * (t1 @ res_w2 + b2)
    sgemm_kernel<0><<<dim3(DIM / 128, NTOK / 128), 256>>>(
        t1b, res_w2, res_b2, rb, NTOK, DIM, DIM, res_logsc, nullptr);
    // 7. gz = LN(concat(x, r))
    ln_concat_kernel<<<NTOK, 256>>>(x, rb, mix_ln_w, mix_ln_b, gzb);
    // 8. g1 = gelu(gz @ gate_w1 + b1)
    sgemm_kernel<1><<<dim3(DIM / 128, NTOK / 128), 256>>>(
        gzb, gate_w1, gate_b1, g1b, NTOK, DIM, 2 * DIM, nullptr, nullptr);
    // 9. g = sigmoid(g1 @ gate_w2 + b2)
    sgemm_kernel<2><<<dim3(DIM / 128, NTOK / 128), 256>>>(
        g1b, gate_w2, gate_b2, gb, NTOK, DIM, DIM, nullptr, nullptr);
    // 10. m = g*r + (1-g)*x
    combine_kernel<<<nelem / 256, 256>>>(gb, rb, x, mb);
    // 11-13. FFN branch (skipped on-device when ffn_alpha == 0)
    ln_kernel<DIM><<<NTOK, 256>>>(mb, ffn_ln_w, ffn_ln_b, lnb, ffn_alpha);
    sgemm_kernel<1><<<dim3(RDIM / 128, NTOK / 128), 256>>>(
        lnb, ffn_w1, ffn_b1, buf2, NTOK, RDIM, DIM, nullptr, ffn_alpha);
    sgemm_kernel<0><<<dim3(DIM / 128, NTOK / 128), 256>>>(
        buf2, ffn_w2, ffn_b2, t1b, NTOK, DIM, RDIM, nullptr, ffn_alpha);
    // 14. out = m + alpha * f
    final_kernel<<<nelem / 256, 256>>>(mb, t1b, ffn_alpha, out);
}

// round 6
// speedup vs baseline: 1.0055x; 1.0055x over previous
#include <cuda_runtime.h>
#include <math.h>

// ---------------------------------------------------------------------------
// ReservoirBlock: B=8, T=2048, D=768, R=3072, HR=768, HF=3072.  All fp32.
// ---------------------------------------------------------------------------

#define NTOK 16384          // B*T
#define DIM  768
#define RDIM 3072
#define TLEN 2048
#define NB   8

#define RBLK 144            // persistent blocks for recurrence
#define SKC  12             // k-chunks
#define KCW  256            // k per chunk

typedef unsigned long long ull;

// ------------------------------ scratch ------------------------------------
__device__ __align__(16) float g_buf1[(size_t)NTOK * RDIM];   // xu -> r_raw (in place)
__device__ __align__(16) float g_buf2[(size_t)NTOK * RDIM];   // rln ; later ffn hidden
__device__ __align__(16) float g_ln  [(size_t)NTOK * DIM];    // LN(x) ; later LN(m)
__device__ __align__(16) float g_t1  [(size_t)NTOK * DIM];    // res-mlp mid ; later f
__device__ __align__(16) float g_r   [(size_t)NTOK * DIM];
__device__ __align__(16) float g_gz  [(size_t)NTOK * 2 * DIM];
__device__ __align__(16) float g_g1  [(size_t)NTOK * DIM];
__device__ __align__(16) float g_g   [(size_t)NTOK * DIM];
__device__ __align__(16) float g_m   [(size_t)NTOK * DIM];
__device__ __align__(16) float g_hbuf[2][RDIM * NB];          // ping-pong state [k][b]
__device__ __align__(16) float2 g_part[SKC * RDIM * 4];       // k-chunk partials
__device__ unsigned g_bar_count;                              // stays 0 between runs
__device__ unsigned g_bar_sense;                              // monotonic

// --------------------------- f32x2 helpers ---------------------------------
__device__ __forceinline__ ull pk2(float x, float y) {
    ull r; asm("mov.b64 %0, {%1, %2};" : "=l"(r) : "f"(x), "f"(y)); return r;
}
__device__ __forceinline__ void fma2(ull &d, ull a, ull b) {
    asm("fma.rn.f32x2 %0, %1, %2, %0;" : "+l"(d) : "l"(a), "l"(b));
}
__device__ __forceinline__ ull add2(ull a, ull b) {
    ull d; asm("add.rn.f32x2 %0, %1, %2;" : "=l"(d) : "l"(a), "l"(b)); return d;
}
__device__ __forceinline__ float2 up2(ull v) {
    float2 f; asm("mov.b64 {%0, %1}, %2;" : "=f"(f.x), "=f"(f.y) : "l"(v)); return f;
}

// --------------------------- grid barrier ----------------------------------
__device__ __forceinline__ void grid_bar(unsigned &sense) {
    sense += 1;
    __threadfence();
    __syncthreads();
    if (threadIdx.x == 0) {
        if (atomicAdd(&g_bar_count, 1u) == RBLK - 1u) {
            g_bar_count = 0u;
            __threadfence();
            *(volatile unsigned *)&g_bar_sense = sense;
        } else {
            while (*(volatile unsigned *)&g_bar_sense != sense) { }
        }
    }
    __syncthreads();
}

// --------------------------- init h ----------------------------------------
__global__ void zero_h_kernel() {
    int i = blockIdx.x * blockDim.x + threadIdx.x;
    if (i < RDIM * NB) g_hbuf[0][i] = 0.0f;
}

// --------------------------- recurrence ------------------------------------
// Persistent: 144 blocks = 12 j-tiles (256 cols) x 12 k-chunks (256 k).
// Thread: 4 consecutive cols, 8 batches packed as 4 f32x2 accumulators.
__global__ void __launch_bounds__(256)
reservoir_kernel(const float* __restrict__ W, float* __restrict__ xu)
{
    __shared__ float h_s[KCW * NB];     // 8 KB: h slice, layout [k][b]
    __shared__ ull   red[256 * 17];     // 34 KB: cross-kgroup reduction

    const int tid = threadIdx.x;
    const int bid = blockIdx.x;
    const int jt  = bid / SKC;
    const int kc  = bid % SKC;
    const int l64 = tid & 63;
    const int kg  = tid >> 6;
    const int col = jt * 256 + l64 * 4;

    unsigned sense = *(volatile unsigned *)&g_bar_sense;   // base (stable pre-barrier)

    #pragma unroll 1
    for (int t = 0; t < TLEN; ++t) {
        const int cur = t & 1;
        const int nxt = cur ^ 1;

        // stage h slice (cross-block data -> .cg to bypass stale L1)
        {
            const float4* src = (const float4*)(g_hbuf[cur] + kc * KCW * NB);
            float4* dst = (float4*)h_s;
            dst[tid]       = __ldcg(src + tid);
            dst[tid + 256] = __ldcg(src + tid + 256);
        }
        __syncthreads();

        ull acc[16];
        #pragma unroll
        for (int q = 0; q < 16; ++q) acc[q] = 0ull;

        const float* wp = W + (size_t)(kc * KCW + kg * 64) * RDIM + col;
        const float* hp = h_s + (kg * 64) * NB;
        #pragma unroll 4
        for (int i = 0; i < 64; ++i) {
            const float4 w4 = *(const float4*)(wp + (size_t)i * RDIM);
            const ulonglong2 hA = *(const ulonglong2*)(hp + i * NB);
            const ulonglong2 hB = *(const ulonglong2*)(hp + i * NB + 4);
            ull s;
            s = pk2(w4.x, w4.x);
            fma2(acc[0],  s, hA.x); fma2(acc[1],  s, hA.y); fma2(acc[2],  s, hB.x); fma2(acc[3],  s, hB.y);
            s = pk2(w4.y, w4.y);
            fma2(acc[4],  s, hA.x); fma2(acc[5],  s, hA.y); fma2(acc[6],  s, hB.x); fma2(acc[7],  s, hB.y);
            s = pk2(w4.z, w4.z);
            fma2(acc[8],  s, hA.x); fma2(acc[9],  s, hA.y); fma2(acc[10], s, hB.x); fma2(acc[11], s, hB.y);
            s = pk2(w4.w, w4.w);
            fma2(acc[12], s, hA.x); fma2(acc[13], s, hA.y); fma2(acc[14], s, hB.x); fma2(acc[15], s, hB.y);
        }

        #pragma unroll
        for (int q = 0; q < 16; ++q) red[tid * 17 + q] = acc[q];
        __syncthreads();

        if (kg == 0) {  // reduce the 4 k-groups, write chunk partials
            #pragma unroll
            for (int q = 0; q < 16; ++q) {
                ull v = red[l64 * 17 + q];
                v = add2(v, red[(l64 + 64)  * 17 + q]);
                v = add2(v, red[(l64 + 128) * 17 + q]);
                v = add2(v, red[(l64 + 192) * 17 + q]);
                const int c = q >> 2, p = q & 3;
                __stcg(&g_part[(kc * RDIM + col + c) * 4 + p], up2(v));
            }
        }
        grid_bar(sense);

        // finalize: sum 12 chunk partials, add xu, tanh, write r + next h
        {
            const int g = bid * 256 + tid;
            if (g < RDIM * 4) {
                const int j = g >> 2, bp = g & 3;
                float sx = 0.0f, sy = 0.0f;
                #pragma unroll
                for (int k2 = 0; k2 < SKC; ++k2) {
                    const float2 p = __ldcg(&g_part[(k2 * RDIM + j) * 4 + bp]);
                    sx += p.x; sy += p.y;
                }
                const size_t i0 = ((size_t)(2 * bp) * TLEN + t) * RDIM + j;
                const size_t i1 = i0 + (size_t)TLEN * RDIM;
                const float v0 = tanhf(sx + xu[i0]);
                const float v1 = tanhf(sy + xu[i1]);
                xu[i0] = v0;   // r stored in place of xu
                xu[i1] = v1;
                __stcg((float2*)(g_hbuf[nxt] + j * NB + 2 * bp), make_float2(v0, v1));
            }
        }
        grid_bar(sense);
    }
}

// --------------------------- activations -----------------------------------
template<int ACT>
__device__ __forceinline__ float act_apply(float v) {
    if (ACT == 1) return 0.5f * v * (1.0f + erff(v * 0.70710678118654752440f)); // exact gelu
    if (ACT == 2) return 1.0f / (1.0f + expf(-v));                              // sigmoid
    return v;
}

// --------------------------- SGEMM 128x128x16 ------------------------------
// C = act(A @ Bw + bias) * exp(*scale_log). A:MxK, Bw:KxN row-major.
// All M,N multiples of 128, K multiples of 16 (no bounds checks).
template<int ACT>
__global__ void __launch_bounds__(256)
sgemm_kernel(const float* __restrict__ A, const float* __restrict__ Bw,
             const float* __restrict__ bias, float* __restrict__ C,
             int M, int N, int K,
             const float* __restrict__ scale_log,
             const float* __restrict__ guard)
{
    if (guard && guard[0] == 0.0f) return;
    __shared__ float As[16 * 132];   // padded: A^T tile
    __shared__ float Bs[16 * 128];

    const int tid = threadIdx.x;
    const int bx = blockIdx.x, by = blockIdx.y;
    const int tx = tid & 15, ty = tid >> 4;
    const int arow = tid >> 2, acol = (tid & 3) << 2;
    const int brow = tid >> 4, bcol = (tid & 15) << 2;
    const size_t abase = (size_t)(by * 128) * K;
    const int cbase = bx * 128;

    ull acc[8][4];
    #pragma unroll
    for (int i = 0; i < 8; ++i)
        #pragma unroll
        for (int j = 0; j < 4; ++j) acc[i][j] = 0ull;

    for (int ko = 0; ko < K; ko += 16) {
        const float4 av0 = *(const float4*)(A + abase + (size_t)arow * K + ko + acol);
        const float4 av1 = *(const float4*)(A + abase + (size_t)(arow + 64) * K + ko + acol);
        const float4 bv0 = *(const float4*)(Bw + (size_t)(ko + brow) * N + cbase + bcol);
        const float4 bv1 = *(const float4*)(Bw + (size_t)(ko + brow) * N + cbase + bcol + 64);
        __syncthreads();
        As[(acol + 0) * 132 + arow] = av0.x;
        As[(acol + 1) * 132 + arow] = av0.y;
        As[(acol + 2) * 132 + arow] = av0.z;
        As[(acol + 3) * 132 + arow] = av0.w;
        As[(acol + 0) * 132 + arow + 64] = av1.x;
        As[(acol + 1) * 132 + arow + 64] = av1.y;
        As[(acol + 2) * 132 + arow + 64] = av1.z;
        As[(acol + 3) * 132 + arow + 64] = av1.w;
        *(float4*)&Bs[brow * 128 + bcol]      = bv0;
        *(float4*)&Bs[brow * 128 + bcol + 64] = bv1;
        __syncthreads();

        #pragma unroll
        for (int kk = 0; kk < 16; ++kk) {
            const float4 a0 = *(const float4*)&As[kk * 132 + ty * 4];
            const float4 a1 = *(const float4*)&As[kk * 132 + 64 + ty * 4];
            const ulonglong2 b01 = *(const ulonglong2*)&Bs[kk * 128 + tx * 4];
            const ulonglong2 b23 = *(const ulonglong2*)&Bs[kk * 128 + tx * 4 + 64];
            ull s;
            s = pk2(a0.x, a0.x); fma2(acc[0][0], s, b01.x); fma2(acc[0][1], s, b01.y); fma2(acc[0][2], s, b23.x); fma2(acc[0][3], s, b23.y);
            s = pk2(a0.y, a0.y); fma2(acc[1][0], s, b01.x); fma2(acc[1][1], s, b01.y); fma2(acc[1][2], s, b23.x); fma2(acc[1][3], s, b23.y);
            s = pk2(a0.z, a0.z); fma2(acc[2][0], s, b01.x); fma2(acc[2][1], s, b01.y); fma2(acc[2][2], s, b23.x); fma2(acc[2][3], s, b23.y);
            s = pk2(a0.w, a0.w); fma2(acc[3][0], s, b01.x); fma2(acc[3][1], s, b01.y); fma2(acc[3][2], s, b23.x); fma2(acc[3][3], s, b23.y);
            s = pk2(a1.x, a1.x); fma2(acc[4][0], s, b01.x); fma2(acc[4][1], s, b01.y); fma2(acc[4][2], s, b23.x); fma2(acc[4][3], s, b23.y);
            s = pk2(a1.y, a1.y); fma2(acc[5][0], s, b01.x); fma2(acc[5][1], s, b01.y); fma2(acc[5][2], s, b23.x); fma2(acc[5][3], s, b23.y);
            s = pk2(a1.z, a1.z); fma2(acc[6][0], s, b01.x); fma2(acc[6][1], s, b01.y); fma2(acc[6][2], s, b23.x); fma2(acc[6][3], s, b23.y);
            s = pk2(a1.w, a1.w); fma2(acc[7][0], s, b01.x); fma2(acc[7][1], s, b01.y); fma2(acc[7][2], s, b23.x); fma2(acc[7][3], s, b23.y);
        }
    }

    float sc = 1.0f;
    if (scale_log) sc = expf(scale_log[0]);
    float4 bb0 = make_float4(0.f, 0.f, 0.f, 0.f), bb1 = bb0;
    if (bias) {
        bb0 = *(const float4*)(bias + cbase + tx * 4);
        bb1 = *(const float4*)(bias + cbase + tx * 4 + 64);
    }
    #pragma unroll
    for (int i = 0; i < 8; ++i) {
        const int r = by * 128 + ((i < 4) ? (ty * 4 + i) : (64 + ty * 4 + i - 4));
        const float2 p0 = up2(acc[i][0]), p1 = up2(acc[i][1]);
        const float2 p2 = up2(acc[i][2]), p3 = up2(acc[i][3]);
        float4 o0, o1;
        o0.x = act_apply<ACT>(p0.x + bb0.x) * sc;
        o0.y = act_apply<ACT>(p0.y + bb0.y) * sc;
        o0.z = act_apply<ACT>(p1.x + bb0.z) * sc;
        o0.w = act_apply<ACT>(p1.y + bb0.w) * sc;
        o1.x = act_apply<ACT>(p2.x + bb1.x) * sc;
        o1.y = act_apply<ACT>(p2.y + bb1.y) * sc;
        o1.z = act_apply<ACT>(p3.x + bb1.z) * sc;
        o1.w = act_apply<ACT>(p3.y + bb1.w) * sc;
        *(float4*)(C + (size_t)r * N + cbase + tx * 4)      = o0;
        *(float4*)(C + (size_t)r * N + cbase + tx * 4 + 64) = o1;
    }
}

// --------------------------- LayerNorm -------------------------------------
__device__ __forceinline__ void blk_reduce2(float &s, float &s2) {
    const unsigned m = 0xffffffffu;
    #pragma unroll
    for (int o = 16; o; o >>= 1) { s += __shfl_xor_sync(m, s, o); s2 += __shfl_xor_sync(m, s2, o); }
    __shared__ float sh[16];
    const int w = threadIdx.x >> 5, l = threadIdx.x & 31;
    if (l == 0) { sh[w] = s; sh[8 + w] = s2; }
    __syncthreads();
    if (threadIdx.x < 32) {
        s  = (l < 8) ? sh[l]     : 0.0f;
        s2 = (l < 8) ? sh[8 + l] : 0.0f;
        #pragma unroll
        for (int o = 4; o; o >>= 1) { s += __shfl_xor_sync(m, s, o); s2 += __shfl_xor_sync(m, s2, o); }
        if (l == 0) { sh[0] = s; sh[8] = s2; }
    }
    __syncthreads();
    s = sh[0]; s2 = sh[8];
}

template<int COLS>
__global__ void __launch_bounds__(256)
ln_kernel(const float* __restrict__ in, const float* __restrict__ w,
          const float* __restrict__ bb, float* __restrict__ out,
          const float* __restrict__ guard)
{
    if (guard && guard[0] == 0.0f) return;
    constexpr int E = COLS / 256;
    const size_t base = (size_t)blockIdx.x * COLS;
    const int tid = threadIdx.x;
    float v[E];
    float s = 0.0f, s2 = 0.0f;
    #pragma unroll
    for (int e = 0; e < E; ++e) {
        const float x = in[base + e * 256 + tid];
        v[e] = x; s += x; s2 += x * x;
    }
    blk_reduce2(s, s2);
    const float mu = s * (1.0f / COLS);
    const float var = s2 * (1.0f / COLS) - mu * mu;
    const float rs = rsqrtf(var + 1e-5f);
    #pragma unroll
    for (int e = 0; e < E; ++e) {
        const int i = e * 256 + tid;
        out[base + i] = (v[e] - mu) * rs * w[i] + bb[i];
    }
}

// LN over concat([x, r]) without materializing the concat
__global__ void __launch_bounds__(256)
ln_concat_kernel(const float* __restrict__ x, const float* __restrict__ r,
                 const float* __restrict__ w, const float* __restrict__ bb,
                 float* __restrict__ out)
{
    constexpr int COLS = 2 * DIM;
    constexpr int E = COLS / 256;
    const int row = blockIdx.x;
    const int tid = threadIdx.x;
    const size_t bx = (size_t)row * DIM;
    const size_t bo = (size_t)row * COLS;
    float v[E];
    float s = 0.0f, s2 = 0.0f;
    #pragma unroll
    for (int e = 0; e < E; ++e) {
        const int i = e * 256 + tid;
        const float val = (i < DIM) ? x[bx + i] : r[bx + i - DIM];
        v[e] = val; s += val; s2 += val * val;
    }
    blk_reduce2(s, s2);
    const float mu = s * (1.0f / COLS);
    const float var = s2 * (1.0f / COLS) - mu * mu;
    const float rs = rsqrtf(var + 1e-5f);
    #pragma unroll
    for (int e = 0; e < E; ++e) {
        const int i = e * 256 + tid;
        out[bo + i] = (v[e] - mu) * rs * w[i] + bb[i];
    }
}

// --------------------------- elementwise -----------------------------------
__global__ void combine_kernel(const float* __restrict__ g, const float* __restrict__ r,
                               const float* __restrict__ x, float* __restrict__ m)
{
    const size_t i = (size_t)blockIdx.x * blockDim.x + threadIdx.x;
    const float gv = g[i];
    m[i] = gv * r[i] + (1.0f - gv) * x[i];
}

__global__ void final_kernel(const float* __restrict__ m, const float* __restrict__ f,
                             const float* __restrict__ alpha, float* __restrict__ out)
{
    const size_t i = (size_t)blockIdx.x * blockDim.x + threadIdx.x;
    const float a = alpha[0];
    float v = m[i];
    if (a != 0.0f) v += a * f[i];
    out[i] = v;
}

// --------------------------- launch ----------------------------------------
extern "C" void kernel_launch(void* const* d_in, const int* in_sizes, int n_in,
                              void* d_out, int out_size)
{
    (void)in_sizes; (void)n_in; (void)out_size;
    const float* x         = (const float*)d_in[0];
    const float* ln_in_w   = (const float*)d_in[1];
    const float* ln_in_b   = (const float*)d_in[2];
    const float* U         = (const float*)d_in[3];
    const float* W         = (const float*)d_in[4];
    const float* res_ln_w  = (const float*)d_in[5];
    const float* res_ln_b  = (const float*)d_in[6];
    const float* res_w1    = (const float*)d_in[7];
    const float* res_b1    = (const float*)d_in[8];
    const float* res_w2    = (const float*)d_in[9];
    const float* res_b2    = (const float*)d_in[10];
    const float* res_logsc = (const float*)d_in[11];
    const float* mix_ln_w  = (const float*)d_in[12];
    const float* mix_ln_b  = (const float*)d_in[13];
    const float* gate_w1   = (const float*)d_in[14];
    const float* gate_b1   = (const float*)d_in[15];
    const float* gate_w2   = (const float*)d_in[16];
    const float* gate_b2   = (const float*)d_in[17];
    const float* ffn_ln_w  = (const float*)d_in[18];
    const float* ffn_ln_b  = (const float*)d_in[19];
    const float* ffn_w1    = (const float*)d_in[20];
    const float* ffn_b1    = (const float*)d_in[21];
    const float* ffn_w2    = (const float*)d_in[22];
    const float* ffn_b2    = (const float*)d_in[23];
    const float* ffn_alpha = (const float*)d_in[24];
    float* out = (float*)d_out;

    float *buf1, *buf2, *lnb, *t1b, *rb, *gzb, *g1b, *gb, *mb;
    cudaGetSymbolAddress((void**)&buf1, g_buf1);
    cudaGetSymbolAddress((void**)&buf2, g_buf2);
    cudaGetSymbolAddress((void**)&lnb,  g_ln);
    cudaGetSymbolAddress((void**)&t1b,  g_t1);
    cudaGetSymbolAddress((void**)&rb,   g_r);
    cudaGetSymbolAddress((void**)&gzb,  g_gz);
    cudaGetSymbolAddress((void**)&g1b,  g_g1);
    cudaGetSymbolAddress((void**)&gb,   g_g);
    cudaGetSymbolAddress((void**)&mb,   g_m);

    const int nelem = NTOK * DIM;

    // 0. reset recurrent state
    zero_h_kernel<<<96, 256>>>();
    // 1. h = LN(x)
    ln_kernel<DIM><<<NTOK, 256>>>(x, ln_in_w, ln_in_b, lnb, nullptr);
    // 2. xu = h @ U   (no bias)
    sgemm_kernel<0><<<dim3(RDIM / 128, NTOK / 128), 256>>>(
        lnb, U, nullptr, buf1, NTOK, RDIM, DIM, nullptr, nullptr);
    // 3. recurrence (writes r over xu in place)
    reservoir_kernel<<<RBLK, 256>>>(W, buf1);
    // 4. rln = LN(r)
    ln_kernel<RDIM><<<NTOK, 256>>>(buf1, res_ln_w, res_ln_b, buf2, nullptr);
    // 5. t1 = gelu(rln @ res_w1 + b1)
    sgemm_kernel<1><<<dim3(DIM / 128, NTOK / 128), 256>>>(
        buf2, res_w1, res_b1, t1b, NTOK, DIM, RDIM, nullptr, nullptr);
    // 6. r = exp(log_scale) * (t1 @ res_w2 + b2)
    sgemm_kernel<0><<<dim3(DIM / 128, NTOK / 128), 256>>>(
        t1b, res_w2, res_b2, rb, NTOK, DIM, DIM, res_logsc, nullptr);
    // 7. gz = LN(concat(x, r))
    ln_concat_kernel<<<NTOK, 256>>>(x, rb, mix_ln_w, mix_ln_b, gzb);
    // 8. g1 = gelu(gz @ gate_w1 + b1)
    sgemm_kernel<1><<<dim3(DIM / 128, NTOK / 128), 256>>>(
        gzb, gate_w1, gate_b1, g1b, NTOK, DIM, 2 * DIM, nullptr, nullptr);
    // 9. g = sigmoid(g1 @ gate_w2 + b2)
    sgemm_kernel<2><<<dim3(DIM / 128, NTOK / 128), 256>>>(
        g1b, gate_w2, gate_b2, gb, NTOK, DIM, DIM, nullptr, nullptr);
    // 10. m = g*r + (1-g)*x
    combine_kernel<<<nelem / 256, 256>>>(gb, rb, x, mb);
    // 11-13. FFN branch (skipped on-device when ffn_alpha == 0)
    ln_kernel<DIM><<<NTOK, 256>>>(mb, ffn_ln_w, ffn_ln_b, lnb, ffn_alpha);
    sgemm_kernel<1><<<dim3(RDIM / 128, NTOK / 128), 256>>>(
        lnb, ffn_w1, ffn_b1, buf2, NTOK, RDIM, DIM, nullptr, ffn_alpha);
    sgemm_kernel<0><<<dim3(DIM / 128, NTOK / 128), 256>>>(
        buf2, ffn_w2, ffn_b2, t1b, NTOK, DIM, RDIM, nullptr, ffn_alpha);
    // 14. out = m + alpha * f
    final_kernel<<<nelem / 256, 256>>>(mb, t1b, ffn_alpha, out);
}

// round 9
// speedup vs baseline: 1.4767x; 1.4686x over previous
#include <cuda_runtime.h>
#include <math.h>

// ---------------------------------------------------------------------------
// ReservoirBlock: B=8, T=2048, D=768, R=3072, HR=768, HF=3072.  All fp32.
// ---------------------------------------------------------------------------

#define NTOK 16384          // B*T
#define DIM  768
#define RDIM 3072
#define TLEN 2048
#define NB   8

// recurrence tiling: 6 j-tiles x 24 k-chunks = 144 persistent blocks
#define JT   6
#define NKC  24
#define JW   512            // cols per block  (RDIM/JT)
#define KW   128            // k per block     (RDIM/NKC)
#define KS   104            // k rows cached in smem (rest streamed from L2)
#define RBLK (JT * NKC)     // 144

typedef unsigned long long ull;

// ------------------------------ scratch ------------------------------------
__device__ __align__(16) float g_buf1[(size_t)NTOK * RDIM];   // xu ; later rln
__device__ __align__(16) float g_buf2[(size_t)NTOK * RDIM];   // r_raw ; later ffn hidden
__device__ __align__(16) float g_ln  [(size_t)NTOK * DIM];
__device__ __align__(16) float g_t1  [(size_t)NTOK * DIM];
__device__ __align__(16) float g_r   [(size_t)NTOK * DIM];
__device__ __align__(16) float g_gz  [(size_t)NTOK * 2 * DIM];
__device__ __align__(16) float g_g1  [(size_t)NTOK * DIM];
__device__ __align__(16) float g_g   [(size_t)NTOK * DIM];
__device__ __align__(16) float g_m   [(size_t)NTOK * DIM];
// chunk partials, ping-pong by step parity: [par][kc][batch-pair][j]
__device__ __align__(16) float2 g_part[2][NKC][4][RDIM];
// two-level barrier state (zero-init; monotonic across replays)
__device__ unsigned g_cnt_grp[12 * 64];   // 12 counters, 256B apart
__device__ unsigned g_cnt_master;
__device__ unsigned g_sense_rel;

// --------------------------- f32x2 helpers ---------------------------------
__device__ __forceinline__ ull pk2(float x, float y) {
    ull r; asm("mov.b64 %0, {%1, %2};" : "=l"(r) : "f"(x), "f"(y)); return r;
}
__device__ __forceinline__ void fma2(ull &d, ull a, ull b) {
    asm("fma.rn.f32x2 %0, %1, %2, %0;" : "+l"(d) : "l"(a), "l"(b));
}
__device__ __forceinline__ float2 up2(ull v) {
    float2 f; asm("mov.b64 {%0, %1}, %2;" : "=f"(f.x), "=f"(f.y) : "l"(v)); return f;
}

// --------------------------- two-level grid barrier -------------------------
// 12 groups of 12 blocks. Monotonic counters + monotonic sense word; modular
// last-arrival check, so no reset is needed (state persists across replays).
__device__ __forceinline__ void grid_bar2(int grp, unsigned &sense) {
    __syncthreads();              // all threads of the block have arrived
    sense += 1;
    if (threadIdx.x == 0) {
        __threadfence();          // order partial stores before arrival
        unsigned a = atomicAdd(&g_cnt_grp[grp << 6], 1u);
        if ((a % 12u) == 11u) {   // last of the group
            __threadfence();
            unsigned b = atomicAdd(&g_cnt_master, 1u);
            if ((b % 12u) == 11u) {   // last group -> release
                atomicExch(&g_sense_rel, sense);
            }
        }
        while ((int)(*(volatile unsigned *)&g_sense_rel - sense) < 0) { }
        __threadfence();          // order subsequent partial reads after spin
    }
    __syncthreads();
}

// --------------------------- recurrence ------------------------------------
// Per block: 512 cols x 128 k.  Thread = 2 adjacent cols x 8 batches
// (8 f32x2 accumulators).  W rows [0,KS) live in smem; rows [KS,KW) stream
// from L2.  One grid barrier per step; each block rebuilds its own next-h
// slice (its k-range) in smem from the chunk partials.
__global__ void __launch_bounds__(256, 1)
reservoir_kernel(const float* __restrict__ W, const float* __restrict__ xu,
                 float* __restrict__ rout)
{
    extern __shared__ float sm[];
    float* W_s = sm;                 // KS*JW floats (208 KB)
    float* h_s = sm + KS * JW;       // KW*NB  floats (4 KB)

    const int tid = threadIdx.x;
    const int bid = blockIdx.x;
    const int jt  = bid / NKC;
    const int kc  = bid % NKC;
    const int grp = bid / 12;

    // preload W rows [0,KS) into smem
    {
        const float4* Wg = (const float4*)(W + (size_t)(kc * KW) * RDIM + jt * JW);
        float4* Ws4 = (float4*)W_s;
        const int n4 = KS * JW / 4;             // 13312
        for (int i = tid; i < n4; i += 256) {
            const int k = i >> 7;               // 128 float4 per row
            const int c = i & 127;
            Ws4[i] = Wg[(size_t)k * (RDIM / 4) + c];
        }
    }
    // zero initial h slice
    for (int i = tid; i < KW * NB; i += 256) h_s[i] = 0.0f;

    unsigned sense = *(volatile unsigned *)&g_sense_rel;   // stable base
    __syncthreads();

    const float* Wstream = W + (size_t)(kc * KW + KS) * RDIM + jt * JW + 2 * tid;
    const int j0 = jt * JW + 2 * tid;           // first of this thread's 2 cols

    // finalize mapping: 256 threads -> 128 j' x 2 batch-halves
    const int fj = kc * KW + (tid & 127);       // column of next-h slice
    const int fh = tid >> 7;                    // 0: batches 0-3, 1: batches 4-7

    #pragma unroll 1
    for (int t = 0; t < TLEN; ++t) {
        const int par = t & 1;

        ull a0 = 0, a1 = 0, a2 = 0, a3 = 0;     // col j0  : batch pairs 0..3
        ull a4 = 0, a5 = 0, a6 = 0, a7 = 0;     // col j0+1: batch pairs 0..3

        // --- compute: smem-resident W rows ---
        #pragma unroll 8
        for (int k = 0; k < KS; ++k) {
            const float2 w = *(const float2*)&W_s[k * JW + 2 * tid];
            const ulonglong2 hA = *(const ulonglong2*)(h_s + k * NB);
            const ulonglong2 hB = *(const ulonglong2*)(h_s + k * NB + 4);
            const ull s0 = pk2(w.x, w.x), s1 = pk2(w.y, w.y);
            fma2(a0, s0, hA.x); fma2(a1, s0, hA.y); fma2(a2, s0, hB.x); fma2(a3, s0, hB.y);
            fma2(a4, s1, hA.x); fma2(a5, s1, hA.y); fma2(a6, s1, hB.x); fma2(a7, s1, hB.y);
        }
        // --- compute: L2-streamed W rows ---
        #pragma unroll 8
        for (int k = 0; k < KW - KS; ++k) {
            const float2 w = __ldg((const float2*)(Wstream + (size_t)k * RDIM));
            const ulonglong2 hA = *(const ulonglong2*)(h_s + (KS + k) * NB);
            const ulonglong2 hB = *(const ulonglong2*)(h_s + (KS + k) * NB + 4);
            const ull s0 = pk2(w.x, w.x), s1 = pk2(w.y, w.y);
            fma2(a0, s0, hA.x); fma2(a1, s0, hA.y); fma2(a2, s0, hB.x); fma2(a3, s0, hB.y);
            fma2(a4, s1, hA.x); fma2(a5, s1, hA.y); fma2(a6, s1, hB.x); fma2(a7, s1, hB.y);
        }

        // --- store chunk partials (layout: [par][kc][pair][j], float2) ---
        {
            const float2 p0 = up2(a0), p1 = up2(a1), p2 = up2(a2), p3 = up2(a3);
            const float2 q0 = up2(a4), q1 = up2(a5), q2 = up2(a6), q3 = up2(a7);
            __stcg((float4*)&g_part[par][kc][0][j0], make_float4(p0.x, p0.y, q0.x, q0.y));
            __stcg((float4*)&g_part[par][kc][1][j0], make_float4(p1.x, p1.y, q1.x, q1.y));
            __stcg((float4*)&g_part[par][kc][2][j0], make_float4(p2.x, p2.y, q2.x, q2.y));
            __stcg((float4*)&g_part[par][kc][3][j0], make_float4(p3.x, p3.y, q3.x, q3.y));
        }

        grid_bar2(grp, sense);

        // --- finalize: rebuild this block's next-h slice locally ---
        {
            float s0x = 0.f, s0y = 0.f, s1x = 0.f, s1y = 0.f;
            #pragma unroll
            for (int c = 0; c < NKC; ++c) {
                const float2 v0 = __ldcg(&g_part[par][c][2 * fh + 0][fj]);
                const float2 v1 = __ldcg(&g_part[par][c][2 * fh + 1][fj]);
                s0x += v0.x; s0y += v0.y; s1x += v1.x; s1y += v1.y;
            }
            const int b0 = 4 * fh;
            const size_t x0 = ((size_t)(b0 + 0) * TLEN + t) * RDIM + fj;
            const size_t x1 = ((size_t)(b0 + 1) * TLEN + t) * RDIM + fj;
            const size_t x2 = ((size_t)(b0 + 2) * TLEN + t) * RDIM + fj;
            const size_t x3 = ((size_t)(b0 + 3) * TLEN + t) * RDIM + fj;
            const float v0 = tanhf(s0x + __ldg(xu + x0));
            const float v1 = tanhf(s0y + __ldg(xu + x1));
            const float v2 = tanhf(s1x + __ldg(xu + x2));
            const float v3 = tanhf(s1y + __ldg(xu + x3));
            *(float4*)&h_s[(tid & 127) * NB + 4 * fh] = make_float4(v0, v1, v2, v3);
            if (jt == 0) {   // one j-tile group publishes r
                __stcg(rout + x0, v0); __stcg(rout + x1, v1);
                __stcg(rout + x2, v2); __stcg(rout + x3, v3);
            }
        }
        __syncthreads();   // h_s ready for next step's compute
    }
}

// --------------------------- activations -----------------------------------
template<int ACT>
__device__ __forceinline__ float act_apply(float v) {
    if (ACT == 1) return 0.5f * v * (1.0f + erff(v * 0.70710678118654752440f)); // exact gelu
    if (ACT == 2) return 1.0f / (1.0f + expf(-v));                              // sigmoid
    return v;
}

// --------------------------- SGEMM 128x128x16 ------------------------------
// C = act(A @ Bw + bias) * exp(*scale_log). A:MxK, Bw:KxN row-major.
// All M,N multiples of 128, K multiples of 16 (no bounds checks).
template<int ACT>
__global__ void __launch_bounds__(256)
sgemm_kernel(const float* __restrict__ A, const float* __restrict__ Bw,
             const float* __restrict__ bias, float* __restrict__ C,
             int M, int N, int K,
             const float* __restrict__ scale_log,
             const float* __restrict__ guard)
{
    if (guard && guard[0] == 0.0f) return;
    __shared__ float As[16 * 132];   // padded: A^T tile
    __shared__ float Bs[16 * 128];

    const int tid = threadIdx.x;
    const int bx = blockIdx.x, by = blockIdx.y;
    const int tx = tid & 15, ty = tid >> 4;
    const int arow = tid >> 2, acol = (tid & 3) << 2;
    const int brow = tid >> 4, bcol = (tid & 15) << 2;
    const size_t abase = (size_t)(by * 128) * K;
    const int cbase = bx * 128;

    ull acc[8][4];
    #pragma unroll
    for (int i = 0; i < 8; ++i)
        #pragma unroll
        for (int j = 0; j < 4; ++j) acc[i][j] = 0ull;

    for (int ko = 0; ko < K; ko += 16) {
        const float4 av0 = *(const float4*)(A + abase + (size_t)arow * K + ko + acol);
        const float4 av1 = *(const float4*)(A + abase + (size_t)(arow + 64) * K + ko + acol);
        const float4 bv0 = *(const float4*)(Bw + (size_t)(ko + brow) * N + cbase + bcol);
        const float4 bv1 = *(const float4*)(Bw + (size_t)(ko + brow) * N + cbase + bcol + 64);
        __syncthreads();
        As[(acol + 0) * 132 + arow] = av0.x;
        As[(acol + 1) * 132 + arow] = av0.y;
        As[(acol + 2) * 132 + arow] = av0.z;
        As[(acol + 3) * 132 + arow] = av0.w;
        As[(acol + 0) * 132 + arow + 64] = av1.x;
        As[(acol + 1) * 132 + arow + 64] = av1.y;
        As[(acol + 2) * 132 + arow + 64] = av1.z;
        As[(acol + 3) * 132 + arow + 64] = av1.w;
        *(float4*)&Bs[brow * 128 + bcol]      = bv0;
        *(float4*)&Bs[brow * 128 + bcol + 64] = bv1;
        __syncthreads();

        #pragma unroll
        for (int kk = 0; kk < 16; ++kk) {
            const float4 a0 = *(const float4*)&As[kk * 132 + ty * 4];
            const float4 a1 = *(const float4*)&As[kk * 132 + 64 + ty * 4];
            const ulonglong2 b01 = *(const ulonglong2*)&Bs[kk * 128 + tx * 4];
            const ulonglong2 b23 = *(const ulonglong2*)&Bs[kk * 128 + tx * 4 + 64];
            ull s;
            s = pk2(a0.x, a0.x); fma2(acc[0][0], s, b01.x); fma2(acc[0][1], s, b01.y); fma2(acc[0][2], s, b23.x); fma2(acc[0][3], s, b23.y);
            s = pk2(a0.y, a0.y); fma2(acc[1][0], s, b01.x); fma2(acc[1][1], s, b01.y); fma2(acc[1][2], s, b23.x); fma2(acc[1][3], s, b23.y);
            s = pk2(a0.z, a0.z); fma2(acc[2][0], s, b01.x); fma2(acc[2][1], s, b01.y); fma2(acc[2][2], s, b23.x); fma2(acc[2][3], s, b23.y);
            s = pk2(a0.w, a0.w); fma2(acc[3][0], s, b01.x); fma2(acc[3][1], s, b01.y); fma2(acc[3][2], s, b23.x); fma2(acc[3][3], s, b23.y);
            s = pk2(a1.x, a1.x); fma2(acc[4][0], s, b01.x); fma2(acc[4][1], s, b01.y); fma2(acc[4][2], s, b23.x); fma2(acc[4][3], s, b23.y);
            s = pk2(a1.y, a1.y); fma2(acc[5][0], s, b01.x); fma2(acc[5][1], s, b01.y); fma2(acc[5][2], s, b23.x); fma2(acc[5][3], s, b23.y);
            s = pk2(a1.z, a1.z); fma2(acc[6][0], s, b01.x); fma2(acc[6][1], s, b01.y); fma2(acc[6][2], s, b23.x); fma2(acc[6][3], s, b23.y);
            s = pk2(a1.w, a1.w); fma2(acc[7][0], s, b01.x); fma2(acc[7][1], s, b01.y); fma2(acc[7][2], s, b23.x); fma2(acc[7][3], s, b23.y);
        }
    }

    float sc = 1.0f;
    if (scale_log) sc = expf(scale_log[0]);
    float4 bb0 = make_float4(0.f, 0.f, 0.f, 0.f), bb1 = bb0;
    if (bias) {
        bb0 = *(const float4*)(bias + cbase + tx * 4);
        bb1 = *(const float4*)(bias + cbase + tx * 4 + 64);
    }
    #pragma unroll
    for (int i = 0; i < 8; ++i) {
        const int r = by * 128 + ((i < 4) ? (ty * 4 + i) : (64 + ty * 4 + i - 4));
        const float2 p0 = up2(acc[i][0]), p1 = up2(acc[i][1]);
        const float2 p2 = up2(acc[i][2]), p3 = up2(acc[i][3]);
        float4 o0, o1;
        o0.x = act_apply<ACT>(p0.x + bb0.x) * sc;
        o0.y = act_apply<ACT>(p0.y + bb0.y) * sc;
        o0.z = act_apply<ACT>(p1.x + bb0.z) * sc;
        o0.w = act_apply<ACT>(p1.y + bb0.w) * sc;
        o1.x = act_apply<ACT>(p2.x + bb1.x) * sc;
        o1.y = act_apply<ACT>(p2.y + bb1.y) * sc;
        o1.z = act_apply<ACT>(p3.x + bb1.z) * sc;
        o1.w = act_apply<ACT>(p3.y + bb1.w) * sc;
        *(float4*)(C + (size_t)r * N + cbase + tx * 4)      = o0;
        *(float4*)(C + (size_t)r * N + cbase + tx * 4 + 64) = o1;
    }
}

// --------------------------- LayerNorm -------------------------------------
__device__ __forceinline__ void blk_reduce2(float &s, float &s2) {
    const unsigned m = 0xffffffffu;
    #pragma unroll
    for (int o = 16; o; o >>= 1) { s += __shfl_xor_sync(m, s, o); s2 += __shfl_xor_sync(m, s2, o); }
    __shared__ float sh[16];
    const int w = threadIdx.x >> 5, l = threadIdx.x & 31;
    if (l == 0) { sh[w] = s; sh[8 + w] = s2; }
    __syncthreads();
    if (threadIdx.x < 32) {
        s  = (l < 8) ? sh[l]     : 0.0f;
        s2 = (l < 8) ? sh[8 + l] : 0.0f;
        #pragma unroll
        for (int o = 4; o; o >>= 1) { s += __shfl_xor_sync(m, s, o); s2 += __shfl_xor_sync(m, s2, o); }
        if (l == 0) { sh[0] = s; sh[8] = s2; }
    }
    __syncthreads();
    s = sh[0]; s2 = sh[8];
}

template<int COLS>
__global__ void __launch_bounds__(256)
ln_kernel(const float* __restrict__ in, const float* __restrict__ w,
          const float* __restrict__ bb, float* __restrict__ out,
          const float* __restrict__ guard)
{
    if (guard && guard[0] == 0.0f) return;
    constexpr int E = COLS / 256;
    const size_t base = (size_t)blockIdx.x * COLS;
    const int tid = threadIdx.x;
    float v[E];
    float s = 0.0f, s2 = 0.0f;
    #pragma unroll
    for (int e = 0; e < E; ++e) {
        const float x = in[base + e * 256 + tid];
        v[e] = x; s += x; s2 += x * x;
    }
    blk_reduce2(s, s2);
    const float mu = s * (1.0f / COLS);
    const float var = s2 * (1.0f / COLS) - mu * mu;
    const float rs = rsqrtf(var + 1e-5f);
    #pragma unroll
    for (int e = 0; e < E; ++e) {
        const int i = e * 256 + tid;
        out[base + i] = (v[e] - mu) * rs * w[i] + bb[i];
    }
}

// LN over concat([x, r]) without materializing the concat
__global__ void __launch_bounds__(256)
ln_concat_kernel(const float* __restrict__ x, const float* __restrict__ r,
                 const float* __restrict__ w, const float* __restrict__ bb,
                 float* __restrict__ out)
{
    constexpr int COLS = 2 * DIM;
    constexpr int E = COLS / 256;
    const int row = blockIdx.x;
    const int tid = threadIdx.x;
    const size_t bx = (size_t)row * DIM;
    const size_t bo = (size_t)row * COLS;
    float v[E];
    float s = 0.0f, s2 = 0.0f;
    #pragma unroll
    for (int e = 0; e < E; ++e) {
        const int i = e * 256 + tid;
        const float val = (i < DIM) ? x[bx + i] : r[bx + i - DIM];
        v[e] = val; s += val; s2 += val * val;
    }
    blk_reduce2(s, s2);
    const float mu = s * (1.0f / COLS);
    const float var = s2 * (1.0f / COLS) - mu * mu;
    const float rs = rsqrtf(var + 1e-5f);
    #pragma unroll
    for (int e = 0; e < E; ++e) {
        const int i = e * 256 + tid;
        out[bo + i] = (v[e] - mu) * rs * w[i] + bb[i];
    }
}

// --------------------------- elementwise -----------------------------------
__global__ void combine_kernel(const float* __restrict__ g, const float* __restrict__ r,
                               const float* __restrict__ x, float* __restrict__ m)
{
    const size_t i = (size_t)blockIdx.x * blockDim.x + threadIdx.x;
    const float gv = g[i];
    m[i] = gv * r[i] + (1.0f - gv) * x[i];
}

__global__ void final_kernel(const float* __restrict__ m, const float* __restrict__ f,
                             const float* __restrict__ alpha, float* __restrict__ out)
{
    const size_t i = (size_t)blockIdx.x * blockDim.x + threadIdx.x;
    const float a = alpha[0];
    float v = m[i];
    if (a != 0.0f) v += a * f[i];
    out[i] = v;
}

// --------------------------- launch ----------------------------------------
extern "C" void kernel_launch(void* const* d_in, const int* in_sizes, int n_in,
                              void* d_out, int out_size)
{
    (void)in_sizes; (void)n_in; (void)out_size;
    const float* x         = (const float*)d_in[0];
    const float* ln_in_w   = (const float*)d_in[1];
    const float* ln_in_b   = (const float*)d_in[2];
    const float* U         = (const float*)d_in[3];
    const float* W         = (const float*)d_in[4];
    const float* res_ln_w  = (const float*)d_in[5];
    const float* res_ln_b  = (const float*)d_in[6];
    const float* res_w1    = (const float*)d_in[7];
    const float* res_b1    = (const float*)d_in[8];
    const float* res_w2    = (const float*)d_in[9];
    const float* res_b2    = (const float*)d_in[10];
    const float* res_logsc = (const float*)d_in[11];
    const float* mix_ln_w  = (const float*)d_in[12];
    const float* mix_ln_b  = (const float*)d_in[13];
    const float* gate_w1   = (const float*)d_in[14];
    const float* gate_b1   = (const float*)d_in[15];
    const float* gate_w2   = (const float*)d_in[16];
    const float* gate_b2   = (const float*)d_in[17];
    const float* ffn_ln_w  = (const float*)d_in[18];
    const float* ffn_ln_b  = (const float*)d_in[19];
    const float* ffn_w1    = (const float*)d_in[20];
    const float* ffn_b1    = (const float*)d_in[21];
    const float* ffn_w2    = (const float*)d_in[22];
    const float* ffn_b2    = (const float*)d_in[23];
    const float* ffn_alpha = (const float*)d_in[24];
    float* out = (float*)d_out;

    float *buf1, *buf2, *lnb, *t1b, *rb, *gzb, *g1b, *gb, *mb;
    cudaGetSymbolAddress((void**)&buf1, g_buf1);
    cudaGetSymbolAddress((void**)&buf2, g_buf2);
    cudaGetSymbolAddress((void**)&lnb,  g_ln);
    cudaGetSymbolAddress((void**)&t1b,  g_t1);
    cudaGetSymbolAddress((void**)&rb,   g_r);
    cudaGetSymbolAddress((void**)&gzb,  g_gz);
    cudaGetSymbolAddress((void**)&g1b,  g_g1);
    cudaGetSymbolAddress((void**)&gb,   g_g);
    cudaGetSymbolAddress((void**)&mb,   g_m);

    const int nelem = NTOK * DIM;
    const int res_smem = (KS * JW + KW * NB) * 4;   // 217088 B
    cudaFuncSetAttribute(reservoir_kernel,
                         cudaFuncAttributeMaxDynamicSharedMemorySize, res_smem);

    // 1. h = LN(x)
    ln_kernel<DIM><<<NTOK, 256>>>(x, ln_in_w, ln_in_b, lnb, nullptr);
    // 2. xu = h @ U   (no bias)
    sgemm_kernel<0><<<dim3(RDIM / 128, NTOK / 128), 256>>>(
        lnb, U, nullptr, buf1, NTOK, RDIM, DIM, nullptr, nullptr);
    // 3. recurrence: reads xu (buf1), writes r_raw -> buf2
    reservoir_kernel<<<RBLK, 256, res_smem>>>(W, buf1, buf2);
    // 4. rln = LN(r_raw)  (buf2 -> buf1; xu dead)
    ln_kernel<RDIM><<<NTOK, 256>>>(buf2, res_ln_w, res_ln_b, buf1, nullptr);
    // 5. t1 = gelu(rln @ res_w1 + b1)
    sgemm_kernel<1><<<dim3(DIM / 128, NTOK / 128), 256>>>(
        buf1, res_w1, res_b1, t1b, NTOK, DIM, RDIM, nullptr, nullptr);
    // 6. r = exp(log_scale) * (t1 @ res_w2 + b2)
    sgemm_kernel<0><<<dim3(DIM / 128, NTOK / 128), 256>>>(
        t1b, res_w2, res_b2, rb, NTOK, DIM, DIM, res_logsc, nullptr);
    // 7. gz = LN(concat(x, r))
    ln_concat_kernel<<<NTOK, 256>>>(x, rb, mix_ln_w, mix_ln_b, gzb);
    // 8. g1 = gelu(gz @ gate_w1 + b1)
    sgemm_kernel<1><<<dim3(DIM / 128, NTOK / 128), 256>>>(
        gzb, gate_w1, gate_b1, g1b, NTOK, DIM, 2 * DIM, nullptr, nullptr);
    // 9. g = sigmoid(g1 @ gate_w2 + b2)
    sgemm_kernel<2><<<dim3(DIM / 128, NTOK / 128), 256>>>(
        g1b, gate_w2, gate_b2, gb, NTOK, DIM, DIM, nullptr, nullptr);
    // 10. m = g*r + (1-g)*x
    combine_kernel<<<nelem / 256, 256>>>(gb, rb, x, mb);
    // 11-13. FFN branch (skipped on-device when ffn_alpha == 0)
    ln_kernel<DIM><<<NTOK, 256>>>(mb, ffn_ln_w, ffn_ln_b, lnb, ffn_alpha);
    sgemm_kernel<1><<<dim3(RDIM / 128, NTOK / 128), 256>>>(
        lnb, ffn_w1, ffn_b1, buf2, NTOK, RDIM, DIM, nullptr, ffn_alpha);
    sgemm_kernel<0><<<dim3(DIM / 128, NTOK / 128), 256>>>(
        buf2, ffn_w2, ffn_b2, t1b, NTOK, DIM, RDIM, nullptr, ffn_alpha);
    // 14. out = m + alpha * f
    final_kernel<<<nelem / 256, 256>>>(mb, t1b, ffn_alpha, out);
}